// round 2
// baseline (speedup 1.0000x reference)
#include <cuda_runtime.h>
#include <math.h>

#define KN 4096
#define CN 10
#define DN 128
#define BN 1000
#define LN 512

// global accumulators (no device allocs allowed)
__device__ double g_sup;
__device__ double g_unsup;
__device__ float  g_sqn[KN];

__global__ void init_kernel() {
    g_sup = 0.0;
    g_unsup = 0.0;
}

// squared norms of embedding rows
__global__ void sqn_kernel(const float* __restrict__ embs) {
    int k = blockIdx.x * blockDim.x + threadIdx.x;
    if (k < KN) {
        const float4* row = (const float4*)(embs + (size_t)k * DN);
        float s = 0.f;
        #pragma unroll
        for (int i = 0; i < DN / 4; i++) {
            float4 v = row[i];
            s += v.x * v.x + v.y * v.y + v.z * v.z + v.w * v.w;
        }
        g_sqn[k] = s;
    }
}

// supervised term: one block (128 threads) per read
__global__ void sup_kernel(const int* __restrict__ reads,
                           const int* __restrict__ labels,
                           const float* __restrict__ embs,
                           const float* __restrict__ W) {
    __shared__ int   s_idx[LN];
    __shared__ float s_re[DN];
    __shared__ float s_logit[16];

    int b = blockIdx.x;
    int t = threadIdx.x;   // 0..127 == embedding dim

    const int* rrow = reads + (size_t)b * LN;
    #pragma unroll
    for (int i = t; i < LN; i += 128) s_idx[i] = rrow[i];
    __syncthreads();

    float re = 0.f;
    #pragma unroll 8
    for (int l = 0; l < LN; l++) {
        re += embs[(size_t)s_idx[l] * DN + t];
    }
    s_re[t] = re;
    __syncthreads();

    int w = t >> 5, lane = t & 31;
    for (int c = w; c < CN; c += 4) {
        float p = 0.f;
        #pragma unroll
        for (int q = 0; q < 4; q++)
            p += s_re[lane + 32 * q] * W[c * DN + lane + 32 * q];
        #pragma unroll
        for (int off = 16; off; off >>= 1)
            p += __shfl_down_sync(0xffffffffu, p, off);
        if (lane == 0) s_logit[c] = p;
    }
    __syncthreads();

    if (t == 0) {
        float m = s_logit[0];
        #pragma unroll
        for (int c = 1; c < CN; c++) m = fmaxf(m, s_logit[c]);
        float se = 0.f;
        #pragma unroll
        for (int c = 0; c < CN; c++) se += expf(s_logit[c] - m);
        float lse = m + logf(se);
        float contrib = lse - s_logit[labels[b]];   // -logp[label]
        atomicAdd(&g_sup, (double)contrib);
    }
}

// unsupervised term: fused tiled Gram + masked distance epilogue.
// Tile: 64 (i) x 64 (j), 256 threads, 4x4 microtile per thread, k split in 2x64.
#define TI 64
#define TJ 64
#define TK 64
#define APAD 68   // row stride in floats (16B-aligned, conflict-light)

__global__ __launch_bounds__(256, 3)
void unsup_kernel(const float* __restrict__ pc,
                  const float* __restrict__ embs) {
    __shared__ float s_a[TI][APAD];   // [i_row][k]       (natural layout)
    __shared__ float s_b[TK][APAD];   // [k][j_row]       (transposed)
    __shared__ float s_red[256];

    int i0 = blockIdx.y * TI;
    int j0 = blockIdx.x * TJ;
    int tid = threadIdx.x;
    int tx = tid & 15;    // j sub
    int ty = tid >> 4;    // i sub

    float acc[4][4] = {};

    for (int kb = 0; kb < DN; kb += TK) {
        // load A tile: 64 rows x 64 k, natural layout, float4 coalesced
        #pragma unroll
        for (int q = 0; q < 4; q++) {
            int idx = tid + 256 * q;         // 0..1023
            int row = idx >> 4;              // 0..63
            int c4  = idx & 15;              // 0..15 -> k = c4*4
            float4 v = *(const float4*)(embs + (size_t)(i0 + row) * DN + kb + c4 * 4);
            *(float4*)&s_a[row][c4 * 4] = v;
        }
        // load B tile transposed: s_b[k][j]
        #pragma unroll
        for (int q = 0; q < 4; q++) {
            int idx = tid + 256 * q;
            int row = idx >> 4;              // j row 0..63
            int c4  = idx & 15;
            float4 v = *(const float4*)(embs + (size_t)(j0 + row) * DN + kb + c4 * 4);
            s_b[c4 * 4 + 0][row] = v.x;
            s_b[c4 * 4 + 1][row] = v.y;
            s_b[c4 * 4 + 2][row] = v.z;
            s_b[c4 * 4 + 3][row] = v.w;
        }
        __syncthreads();

        #pragma unroll
        for (int k = 0; k < TK; k += 4) {
            float4 a4[4], b4[4];
            #pragma unroll
            for (int r = 0; r < 4; r++)
                a4[r] = *(const float4*)&s_a[ty * 4 + r][k];     // row i_r, k..k+3
            #pragma unroll
            for (int q = 0; q < 4; q++)
                b4[q] = *(const float4*)&s_b[k + q][tx * 4];     // k+q, j..j+3

            #pragma unroll
            for (int r = 0; r < 4; r++) {
                const float ar[4] = {a4[r].x, a4[r].y, a4[r].z, a4[r].w};
                #pragma unroll
                for (int q = 0; q < 4; q++) {
                    const float bq[4] = {b4[q].x, b4[q].y, b4[q].z, b4[q].w};
                    #pragma unroll
                    for (int c = 0; c < 4; c++)
                        acc[r][c] = fmaf(ar[q], bq[c], acc[r][c]);
                }
            }
        }
        __syncthreads();
    }

    // epilogue: masked distance terms
    float sqi[4], sqj[4];
    #pragma unroll
    for (int r = 0; r < 4; r++) sqi[r] = g_sqn[i0 + ty * 4 + r];
    #pragma unroll
    for (int c = 0; c < 4; c++) sqj[c] = g_sqn[j0 + tx * 4 + c];

    float local = 0.f;
    #pragma unroll
    for (int r = 0; r < 4; r++) {
        int i = i0 + ty * 4 + r;
        float4 p = *(const float4*)(pc + (size_t)i * KN + j0 + tx * 4);
        const float pv[4] = {p.x, p.y, p.z, p.w};
        #pragma unroll
        for (int c = 0; c < 4; c++) {
            float cnt = pv[c];
            if (cnt != 0.f) {
                float d2 = fmaxf(sqi[r] + sqj[c] - 2.f * acc[r][c], 0.f);
                float dist = sqrtf(d2);
                local += fmaf(cnt, dist, __expf(-dist));
            }
        }
    }

    // block reduce -> double atomic
    s_red[tid] = local;
    __syncthreads();
    #pragma unroll
    for (int s = 128; s >= 32; s >>= 1) {
        if (tid < s) s_red[tid] += s_red[tid + s];
        __syncthreads();
    }
    if (tid < 32) {
        float v = s_red[tid];
        #pragma unroll
        for (int off = 16; off; off >>= 1)
            v += __shfl_down_sync(0xffffffffu, v, off);
        if (tid == 0) atomicAdd(&g_unsup, (double)v);
    }
}

__global__ void final_kernel(const float* __restrict__ delta_p,
                             float* __restrict__ out) {
    float delta = *delta_p;
    double scale = 1.0 / ((double)KN * (double)KN);
    float sup = (float)g_sup;
    float unsup = (float)(g_unsup * scale);
    out[0] = delta * sup + (1.f - delta) * unsup;
}

extern "C" void kernel_launch(void* const* d_in, const int* in_sizes, int n_in,
                              void* d_out, int out_size) {
    const float* pair_counts = (const float*)d_in[0];
    const int*   reads       = (const int*)d_in[1];
    const int*   read_labels = (const int*)d_in[2];
    const float* delta       = (const float*)d_in[3];
    const float* embs        = (const float*)d_in[4];
    const float* softmax_w   = (const float*)d_in[5];
    float* out = (float*)d_out;

    init_kernel<<<1, 1>>>();
    sqn_kernel<<<KN / 128, 128>>>(embs);
    sup_kernel<<<BN, 128>>>(reads, read_labels, embs, softmax_w);
    dim3 ugrid(KN / TJ, KN / TI);
    unsup_kernel<<<ugrid, 256>>>(pair_counts, embs);
    final_kernel<<<1, 1>>>(delta, out);
}

// round 4
// speedup vs baseline: 1.1621x; 1.1621x over previous
#include <cuda_runtime.h>
#include <math.h>

#define KN 4096
#define CN 10
#define DN 128
#define BN 1000
#define LN 512

// global accumulators (no device allocs allowed)
__device__ double g_sup;
__device__ double g_unsup;
__device__ float  g_sqn[KN];

__global__ void init_kernel() {
    g_sup = 0.0;
    g_unsup = 0.0;
}

// squared norms of embedding rows
__global__ void sqn_kernel(const float* __restrict__ embs) {
    int k = blockIdx.x * blockDim.x + threadIdx.x;
    if (k < KN) {
        const float4* row = (const float4*)(embs + (size_t)k * DN);
        float s = 0.f;
        #pragma unroll
        for (int i = 0; i < DN / 4; i++) {
            float4 v = row[i];
            s += v.x * v.x + v.y * v.y + v.z * v.z + v.w * v.w;
        }
        g_sqn[k] = s;
    }
}

// supervised term: one block (128 threads) per read
__global__ void sup_kernel(const int* __restrict__ reads,
                           const int* __restrict__ labels,
                           const float* __restrict__ embs,
                           const float* __restrict__ W) {
    __shared__ int   s_idx[LN];
    __shared__ float s_re[DN];
    __shared__ float s_logit[16];

    int b = blockIdx.x;
    int t = threadIdx.x;   // 0..127 == embedding dim

    const int* rrow = reads + (size_t)b * LN;
    #pragma unroll
    for (int i = t; i < LN; i += 128) s_idx[i] = rrow[i];
    __syncthreads();

    float re = 0.f;
    #pragma unroll 8
    for (int l = 0; l < LN; l++) {
        re += embs[(size_t)s_idx[l] * DN + t];
    }
    s_re[t] = re;
    __syncthreads();

    int w = t >> 5, lane = t & 31;
    for (int c = w; c < CN; c += 4) {
        float p = 0.f;
        #pragma unroll
        for (int q = 0; q < 4; q++)
            p += s_re[lane + 32 * q] * W[c * DN + lane + 32 * q];
        #pragma unroll
        for (int off = 16; off; off >>= 1)
            p += __shfl_down_sync(0xffffffffu, p, off);
        if (lane == 0) s_logit[c] = p;
    }
    __syncthreads();

    if (t == 0) {
        float m = s_logit[0];
        #pragma unroll
        for (int c = 1; c < CN; c++) m = fmaxf(m, s_logit[c]);
        float se = 0.f;
        #pragma unroll
        for (int c = 0; c < CN; c++) se += expf(s_logit[c] - m);
        float lse = m + logf(se);
        float contrib = lse - s_logit[labels[b]];   // -logp[label]
        atomicAdd(&g_sup, (double)contrib);
    }
}

// ---------------------------------------------------------------------------
// unsupervised term: fused tiled Gram + masked distance epilogue.
// Block tile 128x128, 256 threads, 8x8 microtile per thread (split 4+4),
// both operand tiles stored k-major in smem -> 4x LDS.128 per k-step per
// thread feeding 64 FMAs (1 FMA/byte: crossbar and FMA pipe balanced).
// ---------------------------------------------------------------------------
#define TI 128
#define TJ 128
#define TK 32
#define SSTRIDE 132   // 128 + 4 pad (floats)

__global__ __launch_bounds__(256, 2)
void unsup_kernel(const float* __restrict__ pc,
                  const float* __restrict__ embs) {
    __shared__ float s_a[TK][SSTRIDE];   // [k][i]  (k-major)
    __shared__ float s_b[TK][SSTRIDE];   // [k][j]  (k-major)
    __shared__ float s_red[256];

    int i0 = blockIdx.y * TI;
    int j0 = blockIdx.x * TJ;
    int tid = threadIdx.x;
    int tx = tid & 15;    // j sub (16)
    int ty = tid >> 4;    // i sub (16)

    float acc[8][8] = {};

    for (int kb = 0; kb < DN; kb += TK) {
        // load A and B tiles (128 rows x 32 k each), transpose into k-major smem
        #pragma unroll
        for (int q = 0; q < 4; q++) {
            int idx = tid + 256 * q;     // 0..1023
            int row = idx >> 3;          // 0..127
            int c4  = idx & 7;           // k-group 0..7 -> k = c4*4
            float4 va = *(const float4*)(embs + (size_t)(i0 + row) * DN + kb + c4 * 4);
            s_a[c4 * 4 + 0][row] = va.x;
            s_a[c4 * 4 + 1][row] = va.y;
            s_a[c4 * 4 + 2][row] = va.z;
            s_a[c4 * 4 + 3][row] = va.w;
            float4 vb = *(const float4*)(embs + (size_t)(j0 + row) * DN + kb + c4 * 4);
            s_b[c4 * 4 + 0][row] = vb.x;
            s_b[c4 * 4 + 1][row] = vb.y;
            s_b[c4 * 4 + 2][row] = vb.z;
            s_b[c4 * 4 + 3][row] = vb.w;
        }
        __syncthreads();

        #pragma unroll 4
        for (int k = 0; k < TK; k++) {
            float4 alo = *(const float4*)&s_a[k][ty * 4];
            float4 ahi = *(const float4*)&s_a[k][64 + ty * 4];
            float4 blo = *(const float4*)&s_b[k][tx * 4];
            float4 bhi = *(const float4*)&s_b[k][64 + tx * 4];
            const float a[8] = {alo.x, alo.y, alo.z, alo.w,
                                ahi.x, ahi.y, ahi.z, ahi.w};
            const float b[8] = {blo.x, blo.y, blo.z, blo.w,
                                bhi.x, bhi.y, bhi.z, bhi.w};
            #pragma unroll
            for (int r = 0; r < 8; r++)
                #pragma unroll
                for (int c = 0; c < 8; c++)
                    acc[r][c] = fmaf(a[r], b[c], acc[r][c]);
        }
        __syncthreads();
    }

    // epilogue: masked distance terms for the 8x8 microtile
    float sqi[8], sqj[8];
    #pragma unroll
    for (int r = 0; r < 8; r++) {
        int ri = ty * 4 + (r & 3) + ((r >= 4) ? 64 : 0);
        sqi[r] = g_sqn[i0 + ri];
    }
    #pragma unroll
    for (int c = 0; c < 8; c++) {
        int cj = tx * 4 + (c & 3) + ((c >= 4) ? 64 : 0);
        sqj[c] = g_sqn[j0 + cj];
    }

    float local = 0.f;
    #pragma unroll
    for (int r = 0; r < 8; r++) {
        int ri = ty * 4 + (r & 3) + ((r >= 4) ? 64 : 0);
        int i  = i0 + ri;
        float4 p0 = *(const float4*)(pc + (size_t)i * KN + j0 + tx * 4);
        float4 p1 = *(const float4*)(pc + (size_t)i * KN + j0 + 64 + tx * 4);
        const float pv[8] = {p0.x, p0.y, p0.z, p0.w, p1.x, p1.y, p1.z, p1.w};
        #pragma unroll
        for (int c = 0; c < 8; c++) {
            float cnt = pv[c];
            if (cnt != 0.f) {
                float d2 = fmaxf(sqi[r] + sqj[c] - 2.f * acc[r][c], 0.f);
                float dist = sqrtf(d2);
                local += fmaf(cnt, dist, __expf(-dist));
            }
        }
    }

    // block reduce -> double atomic
    s_red[tid] = local;
    __syncthreads();
    #pragma unroll
    for (int s = 128; s >= 32; s >>= 1) {
        if (tid < s) s_red[tid] += s_red[tid + s];
        __syncthreads();
    }
    if (tid < 32) {
        float v = s_red[tid];
        #pragma unroll
        for (int off = 16; off; off >>= 1)
            v += __shfl_down_sync(0xffffffffu, v, off);
        if (tid == 0) atomicAdd(&g_unsup, (double)v);
    }
}

__global__ void final_kernel(const float* __restrict__ delta_p,
                             float* __restrict__ out) {
    float delta = *delta_p;
    double scale = 1.0 / ((double)KN * (double)KN);
    float sup = (float)g_sup;
    float unsup = (float)(g_unsup * scale);
    out[0] = delta * sup + (1.f - delta) * unsup;
}

extern "C" void kernel_launch(void* const* d_in, const int* in_sizes, int n_in,
                              void* d_out, int out_size) {
    const float* pair_counts = (const float*)d_in[0];
    const int*   reads       = (const int*)d_in[1];
    const int*   read_labels = (const int*)d_in[2];
    const float* delta       = (const float*)d_in[3];
    const float* embs        = (const float*)d_in[4];
    const float* softmax_w   = (const float*)d_in[5];
    float* out = (float*)d_out;

    init_kernel<<<1, 1>>>();
    sqn_kernel<<<KN / 128, 128>>>(embs);
    sup_kernel<<<BN, 128>>>(reads, read_labels, embs, softmax_w);
    dim3 ugrid(KN / TJ, KN / TI);
    unsup_kernel<<<ugrid, 256>>>(pair_counts, embs);
    final_kernel<<<1, 1>>>(delta, out);
}

// round 6
// speedup vs baseline: 2.1357x; 1.8378x over previous
#include <cuda_runtime.h>
#include <cuda_bf16.h>
#include <math.h>
#include <stdint.h>

#define KN 4096
#define CN 10
#define DN 128
#define BN 1000
#define LN 512

// global accumulators / scratch (no device allocs allowed)
__device__ double g_sup;
__device__ double g_unsup;
__device__ float  g_sqn[KN];
__device__ __nv_bfloat16 g_embs_bf[KN * DN];   // 1MB bf16 copy of embs

static __device__ __forceinline__ uint32_t smem_u32(const void* p) {
    uint32_t a;
    asm("{ .reg .u64 t; cvta.to.shared.u64 t, %1; cvt.u32.u64 %0, t; }"
        : "=r"(a) : "l"(p));
    return a;
}
static __device__ __forceinline__ void ldsm_x4(uint32_t* r, uint32_t addr) {
    asm volatile("ldmatrix.sync.aligned.m8n8.x4.shared.b16 {%0,%1,%2,%3}, [%4];"
                 : "=r"(r[0]), "=r"(r[1]), "=r"(r[2]), "=r"(r[3]) : "r"(addr));
}
static __device__ __forceinline__ void ldsm_x2(uint32_t* r, uint32_t addr) {
    asm volatile("ldmatrix.sync.aligned.m8n8.x2.shared.b16 {%0,%1}, [%2];"
                 : "=r"(r[0]), "=r"(r[1]) : "r"(addr));
}
static __device__ __forceinline__ void mma_bf16(float* c, const uint32_t* a,
                                                const uint32_t* b) {
    asm volatile(
        "mma.sync.aligned.m16n8k16.row.col.f32.bf16.bf16.f32 "
        "{%0,%1,%2,%3}, {%4,%5,%6,%7}, {%8,%9}, {%0,%1,%2,%3};"
        : "+f"(c[0]), "+f"(c[1]), "+f"(c[2]), "+f"(c[3])
        : "r"(a[0]), "r"(a[1]), "r"(a[2]), "r"(a[3]), "r"(b[0]), "r"(b[1]));
}

// ---------------------------------------------------------------------------
// small kernels
// ---------------------------------------------------------------------------
__global__ void init_kernel() {
    g_sup = 0.0;
    g_unsup = 0.0;
}

__global__ void cvt_kernel(const float* __restrict__ embs) {
    int i = blockIdx.x * blockDim.x + threadIdx.x;   // 131072 threads * 4 elems
    float4 v = *(const float4*)(embs + (size_t)i * 4);
    g_embs_bf[i * 4 + 0] = __float2bfloat16(v.x);
    g_embs_bf[i * 4 + 1] = __float2bfloat16(v.y);
    g_embs_bf[i * 4 + 2] = __float2bfloat16(v.z);
    g_embs_bf[i * 4 + 3] = __float2bfloat16(v.w);
}

__global__ void sqn_kernel(const float* __restrict__ embs) {
    int k = blockIdx.x * blockDim.x + threadIdx.x;
    if (k < KN) {
        const float4* row = (const float4*)(embs + (size_t)k * DN);
        float s = 0.f;
        #pragma unroll
        for (int i = 0; i < DN / 4; i++) {
            float4 v = row[i];
            s += v.x * v.x + v.y * v.y + v.z * v.z + v.w * v.w;
        }
        g_sqn[k] = s;
    }
}

// supervised term: one block (128 threads) per read
__global__ void sup_kernel(const int* __restrict__ reads,
                           const int* __restrict__ labels,
                           const float* __restrict__ embs,
                           const float* __restrict__ W) {
    __shared__ int   s_idx[LN];
    __shared__ float s_re[DN];
    __shared__ float s_logit[16];

    int b = blockIdx.x;
    int t = threadIdx.x;   // 0..127 == embedding dim

    const int* rrow = reads + (size_t)b * LN;
    #pragma unroll
    for (int i = t; i < LN; i += 128) s_idx[i] = rrow[i];
    __syncthreads();

    float re = 0.f;
    #pragma unroll 8
    for (int l = 0; l < LN; l++) {
        re += embs[(size_t)s_idx[l] * DN + t];
    }
    s_re[t] = re;
    __syncthreads();

    int w = t >> 5, lane = t & 31;
    for (int c = w; c < CN; c += 4) {
        float p = 0.f;
        #pragma unroll
        for (int q = 0; q < 4; q++)
            p += s_re[lane + 32 * q] * W[c * DN + lane + 32 * q];
        #pragma unroll
        for (int off = 16; off; off >>= 1)
            p += __shfl_down_sync(0xffffffffu, p, off);
        if (lane == 0) s_logit[c] = p;
    }
    __syncthreads();

    if (t == 0) {
        float m = s_logit[0];
        #pragma unroll
        for (int c = 1; c < CN; c++) m = fmaxf(m, s_logit[c]);
        float se = 0.f;
        #pragma unroll
        for (int c = 0; c < CN; c++) se += expf(s_logit[c] - m);
        float lse = m + logf(se);
        float contrib = lse - s_logit[labels[b]];   // -logp[label]
        atomicAdd(&g_sup, (double)contrib);
    }
}

// ---------------------------------------------------------------------------
// unsupervised term via mma.sync bf16 (HMMA): 128x128 Gram tile per CTA,
// 8 warps (2 m x 4 n), each warp 64x32 = 16 m16n8k16 MMAs per k-step.
// smem row stride 272B makes ldmatrix conflict-free without swizzle.
// Accumulators stay in registers -> direct fused masked-distance epilogue.
// ---------------------------------------------------------------------------
#define SROW 272                     // bytes per smem row (136 bf16)
#define TILE_SM (128 * SROW)         // 34816 B per operand tile
#define USMEM_TOTAL (2 * TILE_SM + 2 * 512 + 64)

__global__ __launch_bounds__(256, 2)
void unsup_mma_kernel(const float* __restrict__ pc) {
    extern __shared__ char dsm[];
    char* s_a = dsm;
    char* s_b = dsm + TILE_SM;
    float* s_sqi = (float*)(dsm + 2 * TILE_SM);
    float* s_sqj = s_sqi + 128;
    float* s_red = s_sqj + 128;

    int tid  = threadIdx.x;
    int wid  = tid >> 5, lane = tid & 31;
    int wm   = wid & 1;          // warp m (2)
    int wn   = wid >> 1;         // warp n (4)
    int i0   = blockIdx.y * 128;
    int j0   = blockIdx.x * 128;

    // load tiles (128 rows x 128 bf16 = 16 x 16B chunks per row)
    const uint4* ga = (const uint4*)(g_embs_bf + (size_t)i0 * DN);
    const uint4* gb = (const uint4*)(g_embs_bf + (size_t)j0 * DN);
    #pragma unroll
    for (int q = 0; q < 8; q++) {
        int idx = tid + 256 * q;      // 0..2047
        int r   = idx >> 4;
        int ch  = idx & 15;
        *(uint4*)(s_a + r * SROW + ch * 16) = ga[r * 16 + ch];
        *(uint4*)(s_b + r * SROW + ch * 16) = gb[r * 16 + ch];
    }
    if (tid < 128) s_sqi[tid] = g_sqn[i0 + tid];
    else           s_sqj[tid - 128] = g_sqn[j0 + tid - 128];
    __syncthreads();

    // ldmatrix base addresses (per-lane)
    uint32_t aAddr = smem_u32(s_a) + (uint32_t)(wm * 64 + (lane & 15)) * SROW
                   + ((lane >> 4) & 1) * 16;
    uint32_t bAddr = smem_u32(s_b) + (uint32_t)(wn * 32 + (lane & 7)) * SROW
                   + ((lane >> 3) & 1) * 16;

    float acc[4][4][4] = {};

    #pragma unroll
    for (int kt = 0; kt < 8; kt++) {
        uint32_t af[4][4], bf[4][2];
        #pragma unroll
        for (int mt = 0; mt < 4; mt++)
            ldsm_x4(af[mt], aAddr + mt * (16 * SROW) + kt * 32);
        #pragma unroll
        for (int nt = 0; nt < 4; nt++)
            ldsm_x2(bf[nt], bAddr + nt * (8 * SROW) + kt * 32);
        #pragma unroll
        for (int mt = 0; mt < 4; mt++)
            #pragma unroll
            for (int nt = 0; nt < 4; nt++)
                mma_bf16(acc[mt][nt], af[mt], bf[nt]);
    }

    // fused epilogue: thread t of the warp owns
    //   c0,c1: (m = mt*16 + t/4,     n = nt*8 + 2*(t%4) + {0,1})
    //   c2,c3: (m = mt*16 + t/4 + 8, same n)
    int tq = lane >> 2;       // 0..7
    int tr = lane & 3;        // 0..3
    float local = 0.f;

    #pragma unroll
    for (int mt = 0; mt < 4; mt++) {
        int mlo = wm * 64 + mt * 16 + tq;     // row within tile
        int mhi = mlo + 8;
        float sqlo = s_sqi[mlo];
        float sqhi = s_sqi[mhi];
        const float* plo = pc + (size_t)(i0 + mlo) * KN + j0;
        const float* phi = pc + (size_t)(i0 + mhi) * KN + j0;
        #pragma unroll
        for (int nt = 0; nt < 4; nt++) {
            int nn = wn * 32 + nt * 8 + tr * 2;
            float2 c0 = *(const float2*)(plo + nn);
            float2 c1 = *(const float2*)(phi + nn);
            float sj0 = s_sqj[nn], sj1 = s_sqj[nn + 1];
            const float cnt[4] = {c0.x, c0.y, c1.x, c1.y};
            const float sqm[4] = {sqlo, sqlo, sqhi, sqhi};
            const float sqn_[4] = {sj0, sj1, sj0, sj1};
            #pragma unroll
            for (int e = 0; e < 4; e++) {
                if (cnt[e] != 0.f) {
                    float d2 = fmaxf(sqm[e] + sqn_[e] - 2.f * acc[mt][nt][e], 0.f);
                    float dist = sqrtf(d2);
                    local += fmaf(cnt[e], dist, __expf(-dist));
                }
            }
        }
    }

    // reduce
    #pragma unroll
    for (int off = 16; off; off >>= 1)
        local += __shfl_down_sync(0xffffffffu, local, off);
    if (lane == 0) s_red[wid] = local;
    __syncthreads();
    if (tid == 0) {
        float v = 0.f;
        #pragma unroll
        for (int w = 0; w < 8; w++) v += s_red[w];
        atomicAdd(&g_unsup, (double)v);
    }
}

__global__ void final_kernel(const float* __restrict__ delta_p,
                             float* __restrict__ out) {
    float delta = *delta_p;
    double scale = 1.0 / ((double)KN * (double)KN);
    float sup = (float)g_sup;
    float unsup = (float)(g_unsup * scale);
    out[0] = delta * sup + (1.f - delta) * unsup;
}

extern "C" void kernel_launch(void* const* d_in, const int* in_sizes, int n_in,
                              void* d_out, int out_size) {
    const float* pair_counts = (const float*)d_in[0];
    const int*   reads       = (const int*)d_in[1];
    const int*   read_labels = (const int*)d_in[2];
    const float* delta       = (const float*)d_in[3];
    const float* embs        = (const float*)d_in[4];
    const float* softmax_w   = (const float*)d_in[5];
    float* out = (float*)d_out;

    cudaFuncSetAttribute(unsup_mma_kernel,
                         cudaFuncAttributeMaxDynamicSharedMemorySize, USMEM_TOTAL);

    init_kernel<<<1, 1>>>();
    cvt_kernel<<<512, 256>>>(embs);
    sqn_kernel<<<KN / 128, 128>>>(embs);
    sup_kernel<<<BN, 128>>>(reads, read_labels, embs, softmax_w);
    dim3 ugrid(KN / 128, KN / 128);
    unsup_mma_kernel<<<ugrid, 256, USMEM_TOTAL>>>(pair_counts);
    final_kernel<<<1, 1>>>(delta, out);
}

// round 8
// speedup vs baseline: 2.5234x; 1.1816x over previous
#include <cuda_runtime.h>
#include <cuda_bf16.h>
#include <math.h>
#include <stdint.h>

#define KN 4096
#define CN 10
#define DN 128
#define BN 1000
#define LN 512

// global accumulators / scratch (no device allocs allowed)
__device__ double g_sup;
__device__ double g_unsup;
__device__ float  g_sqn[KN];
__device__ float  g_P[KN * 16];                // embs @ W.T, padded to 16/row
__device__ __nv_bfloat16 g_embs_bf[KN * DN];   // 1MB bf16 copy of embs

static __device__ __forceinline__ uint32_t smem_u32(const void* p) {
    uint32_t a;
    asm("{ .reg .u64 t; cvta.to.shared.u64 t, %1; cvt.u32.u64 %0, t; }"
        : "=r"(a) : "l"(p));
    return a;
}
static __device__ __forceinline__ void ldsm_x4(uint32_t* r, uint32_t addr) {
    asm volatile("ldmatrix.sync.aligned.m8n8.x4.shared.b16 {%0,%1,%2,%3}, [%4];"
                 : "=r"(r[0]), "=r"(r[1]), "=r"(r[2]), "=r"(r[3]) : "r"(addr));
}
static __device__ __forceinline__ void ldsm_x2(uint32_t* r, uint32_t addr) {
    asm volatile("ldmatrix.sync.aligned.m8n8.x2.shared.b16 {%0,%1}, [%2];"
                 : "=r"(r[0]), "=r"(r[1]) : "r"(addr));
}
static __device__ __forceinline__ void mma_bf16(float* c, const uint32_t* a,
                                                const uint32_t* b) {
    asm volatile(
        "mma.sync.aligned.m16n8k16.row.col.f32.bf16.bf16.f32 "
        "{%0,%1,%2,%3}, {%4,%5,%6,%7}, {%8,%9}, {%0,%1,%2,%3};"
        : "+f"(c[0]), "+f"(c[1]), "+f"(c[2]), "+f"(c[3])
        : "r"(a[0]), "r"(a[1]), "r"(a[2]), "r"(a[3]), "r"(b[0]), "r"(b[1]));
}

// ---------------------------------------------------------------------------
// prep: init accumulators + bf16 convert + sqn + P = embs @ W.T
// grid 512 x 256 threads; one warp per emb row (8 rows per block)
// ---------------------------------------------------------------------------
__global__ __launch_bounds__(256)
void prep_kernel(const float* __restrict__ embs,
                 const float* __restrict__ W) {
    __shared__ float s_w[CN * DN];

    int tid = threadIdx.x;
    if (blockIdx.x == 0 && tid == 0) {
        g_sup = 0.0;
        g_unsup = 0.0;
    }
    for (int i = tid; i < CN * DN; i += 256) s_w[i] = W[i];
    __syncthreads();

    int wid = tid >> 5, lane = tid & 31;
    int row = blockIdx.x * 8 + wid;           // 512*8 = 4096 rows

    const float4 e4 = *(const float4*)(embs + (size_t)row * DN + lane * 4);

    // bf16 convert (4 vals -> 2 x bf16x2 stores)
    __nv_bfloat162* bd = (__nv_bfloat162*)(g_embs_bf + (size_t)row * DN + lane * 4);
    bd[0] = __floats2bfloat162_rn(e4.x, e4.y);
    bd[1] = __floats2bfloat162_rn(e4.z, e4.w);

    // partials: sqn + 10 class dots
    float part[CN + 1];
    part[CN] = e4.x * e4.x + e4.y * e4.y + e4.z * e4.z + e4.w * e4.w;
    #pragma unroll
    for (int c = 0; c < CN; c++) {
        const float4 w4 = *(const float4*)(s_w + c * DN + lane * 4);
        part[c] = e4.x * w4.x + e4.y * w4.y + e4.z * w4.z + e4.w * w4.w;
    }
    #pragma unroll
    for (int off = 16; off; off >>= 1)
        #pragma unroll
        for (int c = 0; c <= CN; c++)
            part[c] += __shfl_down_sync(0xffffffffu, part[c], off);

    if (lane == 0) {
        g_sqn[row] = part[CN];
        #pragma unroll
        for (int c = 0; c < CN; c++) g_P[row * 16 + c] = part[c];
    }
}

// ---------------------------------------------------------------------------
// supervised term via P: logits[b] = sum_l P[reads[b,l]]
// one block (256 threads) per read; 40B gathers instead of 512B rows.
// ---------------------------------------------------------------------------
__global__ __launch_bounds__(256)
void sup2_kernel(const int* __restrict__ reads,
                 const int* __restrict__ labels) {
    __shared__ float s_part[8][CN];
    __shared__ float s_logit[CN];

    int b = blockIdx.x;
    int tid = threadIdx.x;
    int wid = tid >> 5, lane = tid & 31;

    const int* rrow = reads + (size_t)b * LN;
    float acc[CN] = {};
    #pragma unroll
    for (int q = 0; q < LN / 256; q++) {
        int k = rrow[tid + 256 * q];
        const float* pr = g_P + (size_t)k * 16;
        float4 p0 = *(const float4*)(pr);
        float4 p1 = *(const float4*)(pr + 4);
        float2 p2 = *(const float2*)(pr + 8);
        acc[0] += p0.x; acc[1] += p0.y; acc[2] += p0.z; acc[3] += p0.w;
        acc[4] += p1.x; acc[5] += p1.y; acc[6] += p1.z; acc[7] += p1.w;
        acc[8] += p2.x; acc[9] += p2.y;
    }
    #pragma unroll
    for (int off = 16; off; off >>= 1)
        #pragma unroll
        for (int c = 0; c < CN; c++)
            acc[c] += __shfl_down_sync(0xffffffffu, acc[c], off);
    if (lane == 0) {
        #pragma unroll
        for (int c = 0; c < CN; c++) s_part[wid][c] = acc[c];
    }
    __syncthreads();
    if (tid < CN) {
        float v = 0.f;
        #pragma unroll
        for (int w = 0; w < 8; w++) v += s_part[w][tid];
        s_logit[tid] = v;
    }
    __syncthreads();

    if (tid == 0) {
        float m = s_logit[0];
        #pragma unroll
        for (int c = 1; c < CN; c++) m = fmaxf(m, s_logit[c]);
        float se = 0.f;
        #pragma unroll
        for (int c = 0; c < CN; c++) se += expf(s_logit[c] - m);
        float lse = m + logf(se);
        float contrib = lse - s_logit[labels[b]];   // -logp[label]
        atomicAdd(&g_sup, (double)contrib);
    }
}

// ---------------------------------------------------------------------------
// unsupervised term via mma.sync bf16 (HMMA): 128x128 Gram tile per CTA,
// 8 warps (2 m x 4 n), each warp 64x32 = 16 m16n8k16 MMAs per k-step.
// smem row stride 272B makes ldmatrix conflict-free without swizzle.
// Accumulators stay in registers -> direct fused masked-distance epilogue.
// ---------------------------------------------------------------------------
#define SROW 272                     // bytes per smem row (136 bf16)
#define TILE_SM (128 * SROW)         // 34816 B per operand tile
#define USMEM_TOTAL (2 * TILE_SM + 2 * 512 + 64)

__global__ __launch_bounds__(256, 2)
void unsup_mma_kernel(const float* __restrict__ pc) {
    extern __shared__ char dsm[];
    char* s_a = dsm;
    char* s_b = dsm + TILE_SM;
    float* s_sqi = (float*)(dsm + 2 * TILE_SM);
    float* s_sqj = s_sqi + 128;
    float* s_red = s_sqj + 128;

    int tid  = threadIdx.x;
    int wid  = tid >> 5, lane = tid & 31;
    int wm   = wid & 1;          // warp m (2)
    int wn   = wid >> 1;         // warp n (4)
    int i0   = blockIdx.y * 128;
    int j0   = blockIdx.x * 128;

    // load tiles (128 rows x 128 bf16 = 16 x 16B chunks per row)
    const uint4* ga = (const uint4*)(g_embs_bf + (size_t)i0 * DN);
    const uint4* gb = (const uint4*)(g_embs_bf + (size_t)j0 * DN);
    #pragma unroll
    for (int q = 0; q < 8; q++) {
        int idx = tid + 256 * q;      // 0..2047
        int r   = idx >> 4;
        int ch  = idx & 15;
        *(uint4*)(s_a + r * SROW + ch * 16) = ga[r * 16 + ch];
        *(uint4*)(s_b + r * SROW + ch * 16) = gb[r * 16 + ch];
    }
    if (tid < 128) s_sqi[tid] = g_sqn[i0 + tid];
    else           s_sqj[tid - 128] = g_sqn[j0 + tid - 128];
    __syncthreads();

    // ldmatrix base addresses (per-lane)
    uint32_t aAddr = smem_u32(s_a) + (uint32_t)(wm * 64 + (lane & 15)) * SROW
                   + ((lane >> 4) & 1) * 16;
    uint32_t bAddr = smem_u32(s_b) + (uint32_t)(wn * 32 + (lane & 7)) * SROW
                   + ((lane >> 3) & 1) * 16;

    float acc[4][4][4] = {};

    #pragma unroll
    for (int kt = 0; kt < 8; kt++) {
        uint32_t af[4][4], bf[4][2];
        #pragma unroll
        for (int mt = 0; mt < 4; mt++)
            ldsm_x4(af[mt], aAddr + mt * (16 * SROW) + kt * 32);
        #pragma unroll
        for (int nt = 0; nt < 4; nt++)
            ldsm_x2(bf[nt], bAddr + nt * (8 * SROW) + kt * 32);
        #pragma unroll
        for (int mt = 0; mt < 4; mt++)
            #pragma unroll
            for (int nt = 0; nt < 4; nt++)
                mma_bf16(acc[mt][nt], af[mt], bf[nt]);
    }

    // fused epilogue: thread t of the warp owns
    //   c0,c1: (m = mt*16 + t/4,     n = nt*8 + 2*(t%4) + {0,1})
    //   c2,c3: (m = mt*16 + t/4 + 8, same n)
    int tq = lane >> 2;       // 0..7
    int tr = lane & 3;        // 0..3
    float local = 0.f;

    #pragma unroll
    for (int mt = 0; mt < 4; mt++) {
        int mlo = wm * 64 + mt * 16 + tq;     // row within tile
        int mhi = mlo + 8;
        float sqlo = s_sqi[mlo];
        float sqhi = s_sqi[mhi];
        const float* plo = pc + (size_t)(i0 + mlo) * KN + j0;
        const float* phi = pc + (size_t)(i0 + mhi) * KN + j0;
        #pragma unroll
        for (int nt = 0; nt < 4; nt++) {
            int nn = wn * 32 + nt * 8 + tr * 2;
            float2 c0 = *(const float2*)(plo + nn);
            float2 c1 = *(const float2*)(phi + nn);
            float sj0 = s_sqj[nn], sj1 = s_sqj[nn + 1];
            const float cnt[4] = {c0.x, c0.y, c1.x, c1.y};
            const float sqm[4] = {sqlo, sqlo, sqhi, sqhi};
            const float sqn_[4] = {sj0, sj1, sj0, sj1};
            #pragma unroll
            for (int e = 0; e < 4; e++) {
                if (cnt[e] != 0.f) {
                    float d2 = fmaxf(sqm[e] + sqn_[e] - 2.f * acc[mt][nt][e], 0.f);
                    float dist = sqrtf(d2);
                    local += fmaf(cnt[e], dist, __expf(-dist));
                }
            }
        }
    }

    // reduce
    #pragma unroll
    for (int off = 16; off; off >>= 1)
        local += __shfl_down_sync(0xffffffffu, local, off);
    if (lane == 0) s_red[wid] = local;
    __syncthreads();
    if (tid == 0) {
        float v = 0.f;
        #pragma unroll
        for (int w = 0; w < 8; w++) v += s_red[w];
        atomicAdd(&g_unsup, (double)v);
    }
}

__global__ void final_kernel(const float* __restrict__ delta_p,
                             float* __restrict__ out) {
    float delta = *delta_p;
    double scale = 1.0 / ((double)KN * (double)KN);
    float sup = (float)g_sup;
    float unsup = (float)(g_unsup * scale);
    out[0] = delta * sup + (1.f - delta) * unsup;
}

extern "C" void kernel_launch(void* const* d_in, const int* in_sizes, int n_in,
                              void* d_out, int out_size) {
    const float* pair_counts = (const float*)d_in[0];
    const int*   reads       = (const int*)d_in[1];
    const int*   read_labels = (const int*)d_in[2];
    const float* delta       = (const float*)d_in[3];
    const float* embs        = (const float*)d_in[4];
    const float* softmax_w   = (const float*)d_in[5];
    float* out = (float*)d_out;

    cudaFuncSetAttribute(unsup_mma_kernel,
                         cudaFuncAttributeMaxDynamicSharedMemorySize, USMEM_TOTAL);

    prep_kernel<<<512, 256>>>(embs, softmax_w);
    sup2_kernel<<<BN, 256>>>(reads, read_labels);
    dim3 ugrid(KN / 128, KN / 128);
    unsup_mma_kernel<<<ugrid, 256, USMEM_TOTAL>>>(pair_counts);
    final_kernel<<<1, 1>>>(delta, out);
}